// round 1
// baseline (speedup 1.0000x reference)
#include <cuda_runtime.h>
#include <cuda_bf16.h>
#include <math.h>

// Problem constants
#define Bsz 256
#define Nn  128
#define Ff  133
#define Hh  8
#define NHID 64
#define HID 300
#define FP_DIM 1489
#define FP2 512
#define HD (Hh*NHID)   // 512
#define ALPHA 0.2f
#define NEGV (-9e15f)

// ---------------- scratch (device globals; no allocation allowed) ----------------
__device__ float g_Wt [Ff * HD];                 // W_heads transposed to (F, H*NHID)
__device__ float g_Wh [(size_t)Bsz*Nn * HD];     // layer1 features, layout [b,n,h*64+d]
__device__ float g_h  [(size_t)Bsz*Nn * HD];     // layer1 attention output (same layout)
__device__ float g_Wh2[(size_t)Bsz*Nn * HID];    // layer2 features [b,n,hid]
__device__ float g_gat[Bsz * HID];               // mean log_softmax per graph
__device__ float g_t1 [Bsz * FP2];               // fpn hidden
__device__ float g_fpn[Bsz * HID];               // fpn out
__device__ float g_xcat[Bsz * (2*HID)];          // concat(gat2, fpn2)
__device__ float g_y  [Bsz * HID];               // ffn hidden

// ---------------- helpers ----------------
__device__ __forceinline__ float warp_sum(float v) {
    #pragma unroll
    for (int o = 16; o; o >>= 1) v += __shfl_down_sync(0xffffffffu, v, o);
    return v;
}
__device__ __forceinline__ float warp_max(float v) {
    #pragma unroll
    for (int o = 16; o; o >>= 1) v = fmaxf(v, __shfl_down_sync(0xffffffffu, v, o));
    return v;
}

// ---------------- K0: transpose W_heads (H,F,NHID) -> (F, H*NHID) ----------------
__global__ void transpose_wheads(const float* __restrict__ W_heads) {
    int t = blockIdx.x * blockDim.x + threadIdx.x;
    if (t >= Hh * Ff * NHID) return;
    int d = t % NHID;
    int f = (t / NHID) % Ff;
    int h = t / (NHID * Ff);
    g_Wt[f * HD + h * NHID + d] = W_heads[t];
}

// ---------------- generic tiled fp32 GEMM: C = act(A(MxK) * B(KxN) + bias) -------
// act: 0 none, 1 relu.  C row stride = ldc.
__global__ void gemm_rrr(const float* __restrict__ A, const float* __restrict__ Bm,
                         const float* __restrict__ bias, float* __restrict__ C,
                         int M, int N, int K, int ldc, int act)
{
    __shared__ float As[16][68];
    __shared__ float Bs[16][68];
    const int tx = threadIdx.x, ty = threadIdx.y;          // 16x16
    const int tid = ty * 16 + tx;
    const int row0 = blockIdx.y * 64, col0 = blockIdx.x * 64;

    float acc[4][4] = {};
    for (int k0 = 0; k0 < K; k0 += 16) {
        for (int t = tid; t < 64 * 16; t += 256) {
            int m = t >> 4, k = t & 15;
            int gr = row0 + m, gk = k0 + k;
            As[k][m] = (gr < M && gk < K) ? A[(size_t)gr * K + gk] : 0.f;
        }
        for (int t = tid; t < 16 * 64; t += 256) {
            int k = t >> 6, n = t & 63;
            int gk = k0 + k, gc = col0 + n;
            Bs[k][n] = (gk < K && gc < N) ? Bm[(size_t)gk * N + gc] : 0.f;
        }
        __syncthreads();
        #pragma unroll
        for (int k = 0; k < 16; k++) {
            float a[4], b[4];
            #pragma unroll
            for (int i = 0; i < 4; i++) a[i] = As[k][ty + 16 * i];
            #pragma unroll
            for (int j = 0; j < 4; j++) b[j] = Bs[k][tx + 16 * j];
            #pragma unroll
            for (int i = 0; i < 4; i++)
                #pragma unroll
                for (int j = 0; j < 4; j++)
                    acc[i][j] = fmaf(a[i], b[j], acc[i][j]);
        }
        __syncthreads();
    }
    #pragma unroll
    for (int i = 0; i < 4; i++) {
        int r = row0 + ty + 16 * i;
        if (r >= M) continue;
        #pragma unroll
        for (int j = 0; j < 4; j++) {
            int c = col0 + tx + 16 * j;
            if (c >= N) continue;
            float v = acc[i][j];
            if (bias) v += bias[c];
            if (act == 1) v = fmaxf(v, 0.f);
            C[(size_t)r * ldc + c] = v;
        }
    }
}

// ---------------- K2: GAT layer-1 fused attention, one block per (b,h) -----------
__global__ void gat1_kernel(const float* __restrict__ a_heads, const int* __restrict__ adj)
{
    const int b = blockIdx.x >> 3;
    const int h = blockIdx.x & 7;
    __shared__ float Wt[128][65];
    __shared__ float ss[128], dd[128];

    const int tid = threadIdx.x;            // 256
    const int warp = tid >> 5, lane = tid & 31;
    const float* whbase = g_Wh + ((size_t)b * Nn) * HD + h * NHID;

    for (int t = tid; t < 128 * 64; t += 256) {
        int j = t >> 6, d = t & 63;
        Wt[j][d] = whbase[(size_t)j * HD + d];
    }
    __syncthreads();

    const float* a1 = a_heads + h * (2 * NHID);
    const float* a2 = a1 + NHID;
    for (int j = warp; j < 128; j += 8) {
        float s1 = 0.f, s2 = 0.f;
        for (int d = lane; d < 64; d += 32) {
            float w = Wt[j][d];
            s1 = fmaf(w, a1[d], s1);
            s2 = fmaf(w, a2[d], s2);
        }
        s1 = warp_sum(s1); s2 = warp_sum(s2);
        if (lane == 0) { ss[j] = s1; dd[j] = s2; }
    }
    __syncthreads();

    const int* adjb = adj + (size_t)b * Nn * Nn;
    for (int i = warp; i < 128; i += 8) {
        const float si = ss[i];
        const int* ar = adjb + i * Nn;
        float ev[4];
        #pragma unroll
        for (int q = 0; q < 4; q++) {
            int j = lane + q * 32;
            float e = si + dd[j];
            e = (e > 0.f) ? e : ALPHA * e;
            ev[q] = (ar[j] > 0) ? e : NEGV;
        }
        float mx = fmaxf(fmaxf(ev[0], ev[1]), fmaxf(ev[2], ev[3]));
        mx = warp_max(mx);
        mx = __shfl_sync(0xffffffffu, mx, 0);
        float ls = 0.f;
        #pragma unroll
        for (int q = 0; q < 4; q++) { ev[q] = expf(ev[q] - mx); ls += ev[q]; }
        ls = warp_sum(ls);
        ls = __shfl_sync(0xffffffffu, ls, 0);
        const float inv = 1.f / ls;

        float o0 = 0.f, o1 = 0.f;
        #pragma unroll 4
        for (int j = 0; j < 128; j++) {
            float p = __shfl_sync(0xffffffffu, ev[j >> 5], j & 31);
            o0 = fmaf(p, Wt[j][lane], o0);
            o1 = fmaf(p, Wt[j][lane + 32], o1);
        }
        o0 *= inv; o1 *= inv;
        o0 = (o0 > 0.f) ? o0 : expm1f(o0);
        o1 = (o1 > 0.f) ? o1 : expm1f(o1);
        float* out = g_h + ((size_t)(b * Nn + i)) * HD + h * NHID;
        out[lane] = o0;
        out[lane + 32] = o1;
    }
}

// ---------------- K4: GAT layer-2 fused attn + elu + log_softmax + mean ----------
// one block per b, dynamic smem: W[128*304] + ss[128] + dd[128] + acc[8*300]
#define W2LD 304
__global__ void gat2_kernel(const float* __restrict__ a_out, const int* __restrict__ adj)
{
    extern __shared__ float sm[];
    float* W   = sm;                    // 128*304
    float* ss  = W + 128 * W2LD;        // 128
    float* dd  = ss + 128;              // 128
    float* acc = dd + 128;              // 8*300

    const int b = blockIdx.x;
    const int tid = threadIdx.x;        // 256
    const int warp = tid >> 5, lane = tid & 31;

    const float* src = g_Wh2 + (size_t)b * Nn * HID;
    for (int t = tid; t < 128 * HID; t += 256) {
        int j = t / HID, d = t - j * HID;
        W[j * W2LD + d] = src[t];
    }
    for (int t = tid; t < 8 * HID; t += 256) acc[t] = 0.f;
    __syncthreads();

    for (int j = warp; j < 128; j += 8) {
        float s1 = 0.f, s2 = 0.f;
        const float* wr = W + j * W2LD;
        for (int d = lane; d < HID; d += 32) {
            float w = wr[d];
            s1 = fmaf(w, a_out[d], s1);
            s2 = fmaf(w, a_out[HID + d], s2);
        }
        s1 = warp_sum(s1); s2 = warp_sum(s2);
        if (lane == 0) { ss[j] = s1; dd[j] = s2; }
    }
    __syncthreads();

    float* accw = acc + warp * HID;
    const int* adjb = adj + (size_t)b * Nn * Nn;
    for (int i = warp; i < 128; i += 8) {
        const float si = ss[i];
        const int* ar = adjb + i * Nn;
        float ev[4];
        #pragma unroll
        for (int q = 0; q < 4; q++) {
            int j = lane + q * 32;
            float e = si + dd[j];
            e = (e > 0.f) ? e : ALPHA * e;
            ev[q] = (ar[j] > 0) ? e : NEGV;
        }
        float mx = fmaxf(fmaxf(ev[0], ev[1]), fmaxf(ev[2], ev[3]));
        mx = warp_max(mx);
        mx = __shfl_sync(0xffffffffu, mx, 0);
        float ls = 0.f;
        #pragma unroll
        for (int q = 0; q < 4; q++) { ev[q] = expf(ev[q] - mx); ls += ev[q]; }
        ls = warp_sum(ls);
        ls = __shfl_sync(0xffffffffu, ls, 0);
        const float inv = 1.f / ls;

        float o[10];
        #pragma unroll
        for (int t = 0; t < 10; t++) o[t] = 0.f;
        for (int j = 0; j < 128; j++) {
            float p = __shfl_sync(0xffffffffu, ev[j >> 5], j & 31);
            const float* wr = W + j * W2LD;
            #pragma unroll
            for (int t = 0; t < 10; t++) {
                int d = lane + 32 * t;
                if (d < HID) o[t] = fmaf(p, wr[d], o[t]);
            }
        }
        // scale + elu
        #pragma unroll
        for (int t = 0; t < 10; t++) {
            int d = lane + 32 * t;
            if (d < HID) {
                float v = o[t] * inv;
                o[t] = (v > 0.f) ? v : expm1f(v);
            }
        }
        // log_softmax over the 300 values of this row (spread across lanes)
        float m = -1e30f;
        #pragma unroll
        for (int t = 0; t < 10; t++) {
            int d = lane + 32 * t;
            if (d < HID) m = fmaxf(m, o[t]);
        }
        m = warp_max(m);
        m = __shfl_sync(0xffffffffu, m, 0);
        float se = 0.f;
        #pragma unroll
        for (int t = 0; t < 10; t++) {
            int d = lane + 32 * t;
            if (d < HID) se += expf(o[t] - m);
        }
        se = warp_sum(se);
        se = __shfl_sync(0xffffffffu, se, 0);
        const float lse = m + logf(se);
        #pragma unroll
        for (int t = 0; t < 10; t++) {
            int d = lane + 32 * t;
            if (d < HID) accw[d] += o[t] - lse;
        }
    }
    __syncthreads();
    for (int d = tid; d < HID; d += 256) {
        float s = 0.f;
        #pragma unroll
        for (int w = 0; w < 8; w++) s += acc[w * HID + d];
        g_gat[b * HID + d] = s * (1.f / 128.f);
    }
}

// ---------------- K_final: out = sigmoid(y @ ffn_w2 + ffn_b2) --------------------
__global__ void final_kernel(const float* __restrict__ w2, const float* __restrict__ b2,
                             float* __restrict__ out)
{
    const int b = blockIdx.x;
    const int lane = threadIdx.x;   // 32
    float s = 0.f;
    for (int k = lane; k < HID; k += 32) s = fmaf(g_y[b * HID + k], w2[k], s);
    s = warp_sum(s);
    if (lane == 0) {
        float v = s + b2[0];
        out[b] = 1.f / (1.f + expf(-v));
    }
}

// ---------------- launch ----------------
extern "C" void kernel_launch(void* const* d_in, const int* in_sizes, int n_in,
                              void* d_out, int out_size)
{
    const float* atom_feats = (const float*)d_in[0];
    const float* fp         = (const float*)d_in[1];
    const float* W_heads    = (const float*)d_in[2];
    const float* a_heads    = (const float*)d_in[3];
    const float* W_out      = (const float*)d_in[4];
    const float* a_out      = (const float*)d_in[5];
    const float* fc1_w      = (const float*)d_in[6];
    const float* fc1_b      = (const float*)d_in[7];
    const float* fc2_w      = (const float*)d_in[8];
    const float* fc2_b      = (const float*)d_in[9];
    const float* fc_gat_w   = (const float*)d_in[10];
    const float* fc_gat_b   = (const float*)d_in[11];
    const float* fc_fpn_w   = (const float*)d_in[12];
    const float* fc_fpn_b   = (const float*)d_in[13];
    const float* ffn_w1     = (const float*)d_in[14];
    const float* ffn_b1     = (const float*)d_in[15];
    const float* ffn_w2     = (const float*)d_in[16];
    const float* ffn_b2     = (const float*)d_in[17];
    const int*   adj        = (const int*)  d_in[18];
    float* out = (float*)d_out;

    // resolve scratch symbol addresses
    float *pWt, *pWh, *ph, *pWh2, *pgat, *pt1, *pfpn, *pxcat, *py;
    cudaGetSymbolAddress((void**)&pWt,   g_Wt);
    cudaGetSymbolAddress((void**)&pWh,   g_Wh);
    cudaGetSymbolAddress((void**)&ph,    g_h);
    cudaGetSymbolAddress((void**)&pWh2,  g_Wh2);
    cudaGetSymbolAddress((void**)&pgat,  g_gat);
    cudaGetSymbolAddress((void**)&pt1,   g_t1);
    cudaGetSymbolAddress((void**)&pfpn,  g_fpn);
    cudaGetSymbolAddress((void**)&pxcat, g_xcat);
    cudaGetSymbolAddress((void**)&py,    g_y);

    dim3 t16(16, 16);

    // K0: transpose W_heads
    transpose_wheads<<<(Hh * Ff * NHID + 255) / 256, 256>>>(W_heads);

    // K1: Wh = atom_feats(32768x133) @ Wt(133x512)
    gemm_rrr<<<dim3(HD / 64, (Bsz * Nn) / 64), t16>>>(
        atom_feats, pWt, nullptr, pWh, Bsz * Nn, HD, Ff, HD, 0);

    // K2: layer-1 attention
    gat1_kernel<<<Bsz * Hh, 256>>>(a_heads, adj);

    // K3: Wh2 = h(32768x512) @ W_out(512x300)
    gemm_rrr<<<dim3((HID + 63) / 64, (Bsz * Nn) / 64), t16>>>(
        ph, W_out, nullptr, pWh2, Bsz * Nn, HID, HD, HID, 0);

    // K4: layer-2 attention + elu + log_softmax + mean
    const int smem2 = (128 * W2LD + 128 + 128 + 8 * HID) * (int)sizeof(float);
    cudaFuncSetAttribute(gat2_kernel, cudaFuncAttributeMaxDynamicSharedMemorySize, smem2);
    gat2_kernel<<<Bsz, 256, smem2>>>(a_out, adj);

    // FPN branch
    gemm_rrr<<<dim3(FP2 / 64, Bsz / 64), t16>>>(
        fp, fc1_w, fc1_b, pt1, Bsz, FP2, FP_DIM, FP2, 1);
    gemm_rrr<<<dim3((HID + 63) / 64, Bsz / 64), t16>>>(
        pt1, fc2_w, fc2_b, pfpn, Bsz, HID, FP2, HID, 0);

    // gat2 = relu(gat @ fc_gat_w + b) -> xcat[:, :300]
    gemm_rrr<<<dim3((HID + 63) / 64, Bsz / 64), t16>>>(
        pgat, fc_gat_w, fc_gat_b, pxcat, Bsz, HID, HID, 2 * HID, 1);
    // fpn2 = relu(fpn @ fc_fpn_w + b) -> xcat[:, 300:]
    gemm_rrr<<<dim3((HID + 63) / 64, Bsz / 64), t16>>>(
        pfpn, fc_fpn_w, fc_fpn_b, pxcat + HID, Bsz, HID, HID, 2 * HID, 1);

    // y = relu(xcat @ ffn_w1 + b1)
    gemm_rrr<<<dim3((HID + 63) / 64, Bsz / 64), t16>>>(
        pxcat, ffn_w1, ffn_b1, py, Bsz, HID, 2 * HID, HID, 1);

    // out = sigmoid(y @ ffn_w2 + b2)
    final_kernel<<<Bsz, 32>>>(ffn_w2, ffn_b2, out);
}

// round 2
// speedup vs baseline: 1.2764x; 1.2764x over previous
#include <cuda_runtime.h>
#include <cuda_bf16.h>
#include <math.h>

// Problem constants
#define Bsz 256
#define Nn  128
#define Ff  133
#define KP  144          // Ff padded to multiple of 16
#define Hh  8
#define NHID 64
#define HID 300
#define FP_DIM 1489
#define FP2 512
#define HD (Hh*NHID)     // 512
#define ALPHA 0.2f
#define NEGV (-9e15f)

// ---------------- scratch (device globals; no allocation allowed) ----------------
__device__ float g_Apad[(size_t)Bsz*Nn * KP];    // atom_feats zero-padded to K=144
__device__ float g_Wt [KP * HD];                 // W_heads transposed to (KP, H*NHID), pad rows zero
__device__ float g_Wh [(size_t)Bsz*Nn * HD];     // layer1 features [b,n,h*64+d]
__device__ float g_h  [(size_t)Bsz*Nn * HD];     // layer1 attention output
__device__ float g_Wh2[(size_t)Bsz*Nn * HID];    // layer2 features [b,n,hid]
__device__ float g_gat[Bsz * HID];               // mean log_softmax per graph
__device__ float g_t1 [Bsz * FP2];               // fpn hidden (relu(fp@fc1))

// ---------------- helpers ----------------
__device__ __forceinline__ float warp_sum(float v) {
    #pragma unroll
    for (int o = 16; o; o >>= 1) v += __shfl_down_sync(0xffffffffu, v, o);
    return v;
}
__device__ __forceinline__ float warp_max(float v) {
    #pragma unroll
    for (int o = 16; o; o >>= 1) v = fmaxf(v, __shfl_down_sync(0xffffffffu, v, o));
    return v;
}

// ---------------- K0a: pad atom_feats (32768 x 133) -> (32768 x 144) -------------
__global__ void pad_atoms(const float* __restrict__ src) {
    int t = blockIdx.x * blockDim.x + threadIdx.x;
    if (t >= Bsz * Nn * KP) return;
    int k = t % KP;
    int r = t / KP;
    g_Apad[t] = (k < Ff) ? src[(size_t)r * Ff + k] : 0.f;
}

// ---------------- K0b: transpose W_heads (H,F,NHID) -> (KP, H*NHID), zero pad ----
__global__ void transpose_wheads(const float* __restrict__ W_heads) {
    int t = blockIdx.x * blockDim.x + threadIdx.x;
    if (t >= KP * HD) return;
    int f = t / HD;
    int r = t - f * HD;
    int h = r >> 6, d = r & 63;
    g_Wt[t] = (f < Ff) ? W_heads[((size_t)h * Ff + f) * NHID + d] : 0.f;
}

// ---------------- big GEMM: C(MxN) = A(MxK) * B(KxN), M%128==0, K%16==0 ----------
// 128x64 tile, 256 threads, 8x4 accum per thread. A rows must be 16B aligned (K%4==0).
__global__ __launch_bounds__(256) void gemm128(
    const float* __restrict__ A, const float* __restrict__ B,
    float* __restrict__ C, int M, int N, int K, int ldc)
{
    __shared__ float As[128][20];   // [m][k], stride 20 floats (80B, 16B aligned)
    __shared__ float Bs[16][68];    // [k][n]
    const int tid = threadIdx.x;
    const int tx = tid & 15, ty = tid >> 4;
    const int row0 = blockIdx.y * 128, col0 = blockIdx.x * 64;

    float acc[8][4] = {};
    for (int k0 = 0; k0 < K; k0 += 16) {
        // load A tile: 128x16 = 512 float4 slots, 2 per thread
        #pragma unroll
        for (int it = 0; it < 2; it++) {
            int s = tid + it * 256;
            int r = s >> 2, q = (s & 3) << 2;
            float4 v = *reinterpret_cast<const float4*>(A + (size_t)(row0 + r) * K + k0 + q);
            *reinterpret_cast<float4*>(&As[r][q]) = v;
        }
        // load B tile: 16x64 = 256 float4 slots, 1 per thread
        {
            int kk = tid >> 4, n4 = (tid & 15) << 2;
            int gc = col0 + n4;
            float4 v;
            if (gc + 4 <= N) {
                v = *reinterpret_cast<const float4*>(B + (size_t)(k0 + kk) * N + gc);
            } else {
                v.x = (gc + 0 < N) ? B[(size_t)(k0 + kk) * N + gc + 0] : 0.f;
                v.y = (gc + 1 < N) ? B[(size_t)(k0 + kk) * N + gc + 1] : 0.f;
                v.z = (gc + 2 < N) ? B[(size_t)(k0 + kk) * N + gc + 2] : 0.f;
                v.w = (gc + 3 < N) ? B[(size_t)(k0 + kk) * N + gc + 3] : 0.f;
            }
            *reinterpret_cast<float4*>(&Bs[kk][n4]) = v;
        }
        __syncthreads();
        #pragma unroll
        for (int k = 0; k < 16; k++) {
            float a[8], b[4];
            #pragma unroll
            for (int i = 0; i < 8; i++) a[i] = As[ty + 16 * i][k];
            #pragma unroll
            for (int j = 0; j < 4; j++) b[j] = Bs[k][tx + 16 * j];
            #pragma unroll
            for (int i = 0; i < 8; i++)
                #pragma unroll
                for (int j = 0; j < 4; j++)
                    acc[i][j] = fmaf(a[i], b[j], acc[i][j]);
        }
        __syncthreads();
    }
    #pragma unroll
    for (int i = 0; i < 8; i++) {
        int r = row0 + ty + 16 * i;
        #pragma unroll
        for (int j = 0; j < 4; j++) {
            int c = col0 + tx + 16 * j;
            if (c < N) C[(size_t)r * ldc + c] = acc[i][j];
        }
    }
}

// ---------------- generic tiled fp32 GEMM (for fc1): C = act(A*B + bias) ---------
__global__ void gemm_rrr(const float* __restrict__ A, const float* __restrict__ Bm,
                         const float* __restrict__ bias, float* __restrict__ C,
                         int M, int N, int K, int ldc, int act)
{
    __shared__ float As[16][68];
    __shared__ float Bs[16][68];
    const int tx = threadIdx.x, ty = threadIdx.y;
    const int tid = ty * 16 + tx;
    const int row0 = blockIdx.y * 64, col0 = blockIdx.x * 64;

    float acc[4][4] = {};
    for (int k0 = 0; k0 < K; k0 += 16) {
        for (int t = tid; t < 64 * 16; t += 256) {
            int m = t >> 4, k = t & 15;
            int gr = row0 + m, gk = k0 + k;
            As[k][m] = (gr < M && gk < K) ? A[(size_t)gr * K + gk] : 0.f;
        }
        for (int t = tid; t < 16 * 64; t += 256) {
            int k = t >> 6, n = t & 63;
            int gk = k0 + k, gc = col0 + n;
            Bs[k][n] = (gk < K && gc < N) ? Bm[(size_t)gk * N + gc] : 0.f;
        }
        __syncthreads();
        #pragma unroll
        for (int k = 0; k < 16; k++) {
            float a[4], b[4];
            #pragma unroll
            for (int i = 0; i < 4; i++) a[i] = As[k][ty + 16 * i];
            #pragma unroll
            for (int j = 0; j < 4; j++) b[j] = Bs[k][tx + 16 * j];
            #pragma unroll
            for (int i = 0; i < 4; i++)
                #pragma unroll
                for (int j = 0; j < 4; j++)
                    acc[i][j] = fmaf(a[i], b[j], acc[i][j]);
        }
        __syncthreads();
    }
    #pragma unroll
    for (int i = 0; i < 4; i++) {
        int r = row0 + ty + 16 * i;
        if (r >= M) continue;
        #pragma unroll
        for (int j = 0; j < 4; j++) {
            int c = col0 + tx + 16 * j;
            if (c >= N) continue;
            float v = acc[i][j];
            if (bias) v += bias[c];
            if (act == 1) v = fmaxf(v, 0.f);
            C[(size_t)r * ldc + c] = v;
        }
    }
}

// ---------------- K2: GAT layer-1 fused attention, one block per (b,h) -----------
__global__ __launch_bounds__(256) void gat1_kernel(const float* __restrict__ a_heads,
                                                   const int* __restrict__ adj)
{
    const int b = blockIdx.x >> 3;
    const int h = blockIdx.x & 7;
    __shared__ float Wt[128][65];
    __shared__ float ss[128], dd[128];

    const int tid = threadIdx.x;            // 256
    const int warp = tid >> 5, lane = tid & 31;
    const float* whbase = g_Wh + ((size_t)b * Nn) * HD + h * NHID;

    for (int t = tid; t < 128 * 64; t += 256) {
        int j = t >> 6, d = t & 63;
        Wt[j][d] = whbase[(size_t)j * HD + d];
    }
    __syncthreads();

    const float* a1 = a_heads + h * (2 * NHID);
    const float* a2 = a1 + NHID;
    for (int j = warp; j < 128; j += 8) {
        float s1 = 0.f, s2 = 0.f;
        #pragma unroll
        for (int dq = 0; dq < 2; dq++) {
            int d = lane + 32 * dq;
            float w = Wt[j][d];
            s1 = fmaf(w, a1[d], s1);
            s2 = fmaf(w, a2[d], s2);
        }
        s1 = warp_sum(s1); s2 = warp_sum(s2);
        if (lane == 0) { ss[j] = s1; dd[j] = s2; }
    }
    __syncthreads();

    const int* adjb = adj + (size_t)b * Nn * Nn;
    // 4 groups of 4 rows per warp
    for (int g = 0; g < 4; g++) {
        float ev[4][4];
        #pragma unroll
        for (int s = 0; s < 4; s++) {
            const int i = warp + 32 * g + 8 * s;
            const float si = ss[i];
            const int* ar = adjb + i * Nn;
            #pragma unroll
            for (int q = 0; q < 4; q++) {
                int j = lane + q * 32;
                float e = si + dd[j];
                e = (e > 0.f) ? e : ALPHA * e;
                ev[s][q] = (ar[j] > 0) ? e : NEGV;
            }
            float mx = fmaxf(fmaxf(ev[s][0], ev[s][1]), fmaxf(ev[s][2], ev[s][3]));
            mx = warp_max(mx);
            mx = __shfl_sync(0xffffffffu, mx, 0);
            float ls = 0.f;
            #pragma unroll
            for (int q = 0; q < 4; q++) { ev[s][q] = expf(ev[s][q] - mx); ls += ev[s][q]; }
            ls = warp_sum(ls);
            ls = __shfl_sync(0xffffffffu, ls, 0);
            const float inv = 1.f / ls;
            #pragma unroll
            for (int q = 0; q < 4; q++) ev[s][q] *= inv;   // pre-normalize
        }
        // AV: shared Wt loads amortized over 4 rows
        float o0[4] = {}, o1[4] = {};
        #pragma unroll
        for (int jq = 0; jq < 4; jq++) {
            #pragma unroll
            for (int jl = 0; jl < 32; jl++) {
                const int j = jq * 32 + jl;
                float w0 = Wt[j][lane];
                float w1 = Wt[j][lane + 32];
                #pragma unroll
                for (int s = 0; s < 4; s++) {
                    float p = __shfl_sync(0xffffffffu, ev[s][jq], jl);
                    o0[s] = fmaf(p, w0, o0[s]);
                    o1[s] = fmaf(p, w1, o1[s]);
                }
            }
        }
        #pragma unroll
        for (int s = 0; s < 4; s++) {
            const int i = warp + 32 * g + 8 * s;
            float v0 = o0[s], v1 = o1[s];
            v0 = (v0 > 0.f) ? v0 : expm1f(v0);
            v1 = (v1 > 0.f) ? v1 : expm1f(v1);
            float* out = g_h + ((size_t)(b * Nn + i)) * HD + h * NHID;
            out[lane] = v0;
            out[lane + 32] = v1;
        }
    }
}

// ---------------- K4: GAT layer-2 fused attn + elu + log_softmax + mean ----------
#define W2LD 304
__global__ __launch_bounds__(256) void gat2_kernel(const float* __restrict__ a_out,
                                                   const int* __restrict__ adj)
{
    extern __shared__ float sm[];
    float* W   = sm;                    // 128*304
    float* ss  = W + 128 * W2LD;        // 128
    float* dd  = ss + 128;              // 128
    float* acc = dd + 128;              // 8*300

    const int b = blockIdx.x;
    const int tid = threadIdx.x;        // 256
    const int warp = tid >> 5, lane = tid & 31;

    const float* src = g_Wh2 + (size_t)b * Nn * HID;
    for (int t = tid; t < 128 * HID; t += 256) {
        int j = t / HID, d = t - j * HID;
        W[j * W2LD + d] = src[t];
    }
    for (int t = tid; t < 8 * HID; t += 256) acc[t] = 0.f;
    __syncthreads();

    for (int j = warp; j < 128; j += 8) {
        float s1 = 0.f, s2 = 0.f;
        const float* wr = W + j * W2LD;
        for (int d = lane; d < HID; d += 32) {
            float w = wr[d];
            s1 = fmaf(w, a_out[d], s1);
            s2 = fmaf(w, a_out[HID + d], s2);
        }
        s1 = warp_sum(s1); s2 = warp_sum(s2);
        if (lane == 0) { ss[j] = s1; dd[j] = s2; }
    }
    __syncthreads();

    float* accw = acc + warp * HID;
    const int* adjb = adj + (size_t)b * Nn * Nn;
    // 8 groups of 2 rows per warp
    for (int g = 0; g < 8; g++) {
        float ev[2][4];
        #pragma unroll
        for (int s = 0; s < 2; s++) {
            const int i = warp + 16 * g + 8 * s;
            const float si = ss[i];
            const int* ar = adjb + i * Nn;
            #pragma unroll
            for (int q = 0; q < 4; q++) {
                int j = lane + q * 32;
                float e = si + dd[j];
                e = (e > 0.f) ? e : ALPHA * e;
                ev[s][q] = (ar[j] > 0) ? e : NEGV;
            }
            float mx = fmaxf(fmaxf(ev[s][0], ev[s][1]), fmaxf(ev[s][2], ev[s][3]));
            mx = warp_max(mx);
            mx = __shfl_sync(0xffffffffu, mx, 0);
            float ls = 0.f;
            #pragma unroll
            for (int q = 0; q < 4; q++) { ev[s][q] = expf(ev[s][q] - mx); ls += ev[s][q]; }
            ls = warp_sum(ls);
            ls = __shfl_sync(0xffffffffu, ls, 0);
            const float inv = 1.f / ls;
            #pragma unroll
            for (int q = 0; q < 4; q++) ev[s][q] *= inv;
        }

        float o0[10] = {}, o1[10] = {};
        #pragma unroll
        for (int jq = 0; jq < 4; jq++) {
            for (int jl = 0; jl < 32; jl++) {
                const int j = jq * 32 + jl;
                const float* wr = W + j * W2LD;
                float p0 = __shfl_sync(0xffffffffu, ev[0][jq], jl);
                float p1 = __shfl_sync(0xffffffffu, ev[1][jq], jl);
                #pragma unroll
                for (int t = 0; t < 10; t++) {
                    int d = lane + 32 * t;
                    if (d < HID) {
                        float w = wr[d];
                        o0[t] = fmaf(p0, w, o0[t]);
                        o1[t] = fmaf(p1, w, o1[t]);
                    }
                }
            }
        }
        // per-row: elu + log_softmax, then accumulate both rows
        #pragma unroll
        for (int s = 0; s < 2; s++) {
            float* o = (s == 0) ? o0 : o1;
            #pragma unroll
            for (int t = 0; t < 10; t++) {
                int d = lane + 32 * t;
                if (d < HID) o[t] = (o[t] > 0.f) ? o[t] : expm1f(o[t]);
            }
            float m = -1e30f;
            #pragma unroll
            for (int t = 0; t < 10; t++) {
                int d = lane + 32 * t;
                if (d < HID) m = fmaxf(m, o[t]);
            }
            m = warp_max(m);
            m = __shfl_sync(0xffffffffu, m, 0);
            float se = 0.f;
            #pragma unroll
            for (int t = 0; t < 10; t++) {
                int d = lane + 32 * t;
                if (d < HID) se += expf(o[t] - m);
            }
            se = warp_sum(se);
            se = __shfl_sync(0xffffffffu, se, 0);
            const float lse = m + logf(se);
            #pragma unroll
            for (int t = 0; t < 10; t++) {
                int d = lane + 32 * t;
                if (d < HID) accw[d] += o[t] - lse;
            }
        }
    }
    __syncthreads();
    for (int d = tid; d < HID; d += 256) {
        float s = 0.f;
        #pragma unroll
        for (int w = 0; w < 8; w++) s += acc[w * HID + d];
        g_gat[b * HID + d] = s * (1.f / 128.f);
    }
}

// ---------------- head: fc2 + fc_gat + fc_fpn + ffn1 + ffn2 + sigmoid ------------
#define HB 4
__global__ __launch_bounds__(256) void head_fused(
    const float* __restrict__ fc2_w, const float* __restrict__ fc2_b,
    const float* __restrict__ Wg,    const float* __restrict__ bg,
    const float* __restrict__ Wf,    const float* __restrict__ bf,
    const float* __restrict__ W1,    const float* __restrict__ b1,
    const float* __restrict__ w2,    const float* __restrict__ b2,
    float* __restrict__ out)
{
    __shared__ float t1s [HB][512];
    __shared__ float gats[HB][HID];
    __shared__ float fpns[HB][HID];
    __shared__ float us  [HB][HID];
    __shared__ float vs  [HB][HID];
    __shared__ float ys  [HB][HID];

    const int b0 = blockIdx.x * HB;
    const int tid = threadIdx.x;

    for (int t = tid; t < HB * 512; t += 256) {
        int r = t >> 9;
        t1s[r][t & 511] = g_t1[(size_t)(b0 + r) * FP2 + (t & 511)];
    }
    for (int t = tid; t < HB * HID; t += 256) {
        int r = t / HID, c = t - r * HID;
        gats[r][c] = g_gat[(size_t)(b0 + r) * HID + c];
    }
    __syncthreads();

    // stage 1: fpn = t1 @ fc2_w + fc2_b (no relu)
    for (int c = tid; c < HID; c += 256) {
        float a[HB] = {};
        #pragma unroll 4
        for (int k = 0; k < 512; k++) {
            float w = fc2_w[(size_t)k * HID + c];
            #pragma unroll
            for (int r = 0; r < HB; r++) a[r] = fmaf(t1s[r][k], w, a[r]);
        }
        float bb = fc2_b[c];
        #pragma unroll
        for (int r = 0; r < HB; r++) fpns[r][c] = a[r] + bb;
    }
    __syncthreads();

    // stage 2: u = relu(gat @ Wg + bg), v = relu(fpn @ Wf + bf)
    for (int c = tid; c < HID; c += 256) {
        float a[HB] = {}, e[HB] = {};
        #pragma unroll 4
        for (int k = 0; k < HID; k++) {
            float wg = Wg[(size_t)k * HID + c];
            float wf = Wf[(size_t)k * HID + c];
            #pragma unroll
            for (int r = 0; r < HB; r++) {
                a[r] = fmaf(gats[r][k], wg, a[r]);
                e[r] = fmaf(fpns[r][k], wf, e[r]);
            }
        }
        float bbg = bg[c], bbf = bf[c];
        #pragma unroll
        for (int r = 0; r < HB; r++) {
            us[r][c] = fmaxf(a[r] + bbg, 0.f);
            vs[r][c] = fmaxf(e[r] + bbf, 0.f);
        }
    }
    __syncthreads();

    // stage 3: y = relu([u v] @ W1 + b1)
    for (int c = tid; c < HID; c += 256) {
        float a[HB] = {};
        #pragma unroll 4
        for (int k = 0; k < HID; k++) {
            float w = W1[(size_t)k * HID + c];
            #pragma unroll
            for (int r = 0; r < HB; r++) a[r] = fmaf(us[r][k], w, a[r]);
        }
        #pragma unroll 4
        for (int k = 0; k < HID; k++) {
            float w = W1[(size_t)(k + HID) * HID + c];
            #pragma unroll
            for (int r = 0; r < HB; r++) a[r] = fmaf(vs[r][k], w, a[r]);
        }
        float bb = b1[c];
        #pragma unroll
        for (int r = 0; r < HB; r++) ys[r][c] = fmaxf(a[r] + bb, 0.f);
    }
    __syncthreads();

    // stage 4: out = sigmoid(y . w2 + b2)
    const int warp = tid >> 5, lane = tid & 31;
    if (warp < HB) {
        float s = 0.f;
        for (int k = lane; k < HID; k += 32) s = fmaf(ys[warp][k], w2[k], s);
        s = warp_sum(s);
        if (lane == 0) out[b0 + warp] = 1.f / (1.f + expf(-(s + b2[0])));
    }
}

// ---------------- launch ----------------
extern "C" void kernel_launch(void* const* d_in, const int* in_sizes, int n_in,
                              void* d_out, int out_size)
{
    const float* atom_feats = (const float*)d_in[0];
    const float* fp         = (const float*)d_in[1];
    const float* W_heads    = (const float*)d_in[2];
    const float* a_heads    = (const float*)d_in[3];
    const float* W_out      = (const float*)d_in[4];
    const float* a_out      = (const float*)d_in[5];
    const float* fc1_w      = (const float*)d_in[6];
    const float* fc1_b      = (const float*)d_in[7];
    const float* fc2_w      = (const float*)d_in[8];
    const float* fc2_b      = (const float*)d_in[9];
    const float* fc_gat_w   = (const float*)d_in[10];
    const float* fc_gat_b   = (const float*)d_in[11];
    const float* fc_fpn_w   = (const float*)d_in[12];
    const float* fc_fpn_b   = (const float*)d_in[13];
    const float* ffn_w1     = (const float*)d_in[14];
    const float* ffn_b1     = (const float*)d_in[15];
    const float* ffn_w2     = (const float*)d_in[16];
    const float* ffn_b2     = (const float*)d_in[17];
    const int*   adj        = (const int*)  d_in[18];
    float* out = (float*)d_out;

    float *pApad, *pWt, *pWh, *ph, *pWh2, *pt1;
    cudaGetSymbolAddress((void**)&pApad, g_Apad);
    cudaGetSymbolAddress((void**)&pWt,   g_Wt);
    cudaGetSymbolAddress((void**)&pWh,   g_Wh);
    cudaGetSymbolAddress((void**)&ph,    g_h);
    cudaGetSymbolAddress((void**)&pWh2,  g_Wh2);
    cudaGetSymbolAddress((void**)&pt1,   g_t1);

    dim3 t16(16, 16);

    // prep: pad A, transpose weights
    pad_atoms<<<(Bsz * Nn * KP + 255) / 256, 256>>>(atom_feats);
    transpose_wheads<<<(KP * HD + 255) / 256, 256>>>(W_heads);

    // fc1 (independent branch): t1 = relu(fp @ fc1_w + fc1_b)
    gemm_rrr<<<dim3(FP2 / 64, Bsz / 64), t16>>>(
        fp, fc1_w, fc1_b, pt1, Bsz, FP2, FP_DIM, FP2, 1);

    // K1: Wh = Apad(32768x144) @ Wt(144x512)
    gemm128<<<dim3(HD / 64, (Bsz * Nn) / 128), 256>>>(
        pApad, pWt, pWh, Bsz * Nn, HD, KP, HD);

    // K2: layer-1 attention
    gat1_kernel<<<Bsz * Hh, 256>>>(a_heads, adj);

    // K3: Wh2 = h(32768x512) @ W_out(512x300)
    gemm128<<<dim3((HID + 63) / 64, (Bsz * Nn) / 128), 256>>>(
        ph, W_out, pWh2, Bsz * Nn, HID, HD, HID);

    // K4: layer-2 attention + elu + log_softmax + mean
    const int smem2 = (128 * W2LD + 128 + 128 + 8 * HID) * (int)sizeof(float);
    cudaFuncSetAttribute(gat2_kernel, cudaFuncAttributeMaxDynamicSharedMemorySize, smem2);
    gat2_kernel<<<Bsz, 256, smem2>>>(a_out, adj);

    // fused head: fc2 + fc_gat + fc_fpn + ffn1 + ffn2 + sigmoid
    head_fused<<<Bsz / HB, 256>>>(
        fc2_w, fc2_b, fc_gat_w, fc_gat_b, fc_fpn_w, fc_fpn_b,
        ffn_w1, ffn_b1, ffn_w2, ffn_b2, out);
}

// round 3
// speedup vs baseline: 1.7068x; 1.3372x over previous
#include <cuda_runtime.h>
#include <cuda_bf16.h>
#include <math.h>

// Problem constants
#define Bsz 256
#define Nn  128
#define Ff  133
#define KP  144          // Ff padded to multiple of 16
#define Hh  8
#define NHID 64
#define HID 300
#define FP_DIM 1489
#define KP1 1536         // FP_DIM padded
#define FSPLIT 8
#define FCHUNK 192       // KP1 / FSPLIT, multiple of 16
#define FP2 512
#define HD (Hh*NHID)     // 512
#define ALPHA 0.2f
#define NEGV (-9e15f)

// ---------------- scratch (device globals; no allocation allowed) ----------------
__device__ float g_Apad[(size_t)Bsz*Nn * KP];    // atom_feats zero-padded to K=144
__device__ float g_Wt  [KP * HD];                // W_heads transposed (KP, H*NHID)
__device__ float g_Wh  [(size_t)Bsz*Nn * HD];    // layer1 features [b,n,h*64+d]
__device__ float g_h   [(size_t)Bsz*Nn * HD];    // layer1 attention output
__device__ float g_Wh2 [(size_t)Bsz*Nn * HID];   // layer2 features [b,n,hid]
__device__ float g_ss2 [Bsz * Nn];               // layer2 source scores
__device__ float g_dd2 [Bsz * Nn];               // layer2 dest scores
__device__ float g_P   [(size_t)Bsz*Nn * Nn];    // layer2 probs
__device__ float g_O   [(size_t)Bsz*Nn * HID];   // layer2 elu(attn@Wh2)
__device__ float g_gat [Bsz * HID];              // mean log_softmax per graph
__device__ float g_fppad[(size_t)Bsz * KP1];     // fp zero-padded
__device__ float g_w1pad[(size_t)KP1 * FP2];     // fc1_w zero-padded
__device__ float g_part[(size_t)FSPLIT * Bsz * FP2]; // fc1 split-K partials
__device__ float g_t1  [Bsz * FP2];              // fpn hidden (relu(fp@fc1))

// ---------------- helpers ----------------
__device__ __forceinline__ float warp_sum(float v) {
    #pragma unroll
    for (int o = 16; o; o >>= 1) v += __shfl_down_sync(0xffffffffu, v, o);
    return v;
}
__device__ __forceinline__ float warp_max(float v) {
    #pragma unroll
    for (int o = 16; o; o >>= 1) v = fmaxf(v, __shfl_down_sync(0xffffffffu, v, o));
    return v;
}

// ---------------- pad kernels ----------------------------------------------------
__global__ void pad_atoms(const float* __restrict__ src) {
    int t = blockIdx.x * blockDim.x + threadIdx.x;
    if (t >= Bsz * Nn * KP) return;
    int k = t % KP;
    int r = t / KP;
    g_Apad[t] = (k < Ff) ? src[(size_t)r * Ff + k] : 0.f;
}
__global__ void transpose_wheads(const float* __restrict__ W_heads) {
    int t = blockIdx.x * blockDim.x + threadIdx.x;
    if (t >= KP * HD) return;
    int f = t / HD;
    int r = t - f * HD;
    int h = r >> 6, d = r & 63;
    g_Wt[t] = (f < Ff) ? W_heads[((size_t)h * Ff + f) * NHID + d] : 0.f;
}
__global__ void pad_fp(const float* __restrict__ fp) {
    int t = blockIdx.x * blockDim.x + threadIdx.x;
    if (t >= Bsz * KP1) return;
    int k = t % KP1, r = t / KP1;
    g_fppad[t] = (k < FP_DIM) ? fp[(size_t)r * FP_DIM + k] : 0.f;
}
__global__ void pad_w1(const float* __restrict__ w) {
    int t = blockIdx.x * blockDim.x + threadIdx.x;
    if (t >= KP1 * FP2) return;
    int r = t / FP2;
    g_w1pad[t] = (r < FP_DIM) ? w[t] : 0.f;
}

// ---------------- big GEMM: C(MxN) = A(MxK) * B(KxN), M%128==0, K%16==0 ----------
__global__ __launch_bounds__(256) void gemm128(
    const float* __restrict__ A, const float* __restrict__ B,
    float* __restrict__ C, int M, int N, int K, int ldc)
{
    __shared__ float As[128][20];
    __shared__ float Bs[16][68];
    const int tid = threadIdx.x;
    const int tx = tid & 15, ty = tid >> 4;
    const int row0 = blockIdx.y * 128, col0 = blockIdx.x * 64;

    float acc[8][4] = {};
    for (int k0 = 0; k0 < K; k0 += 16) {
        #pragma unroll
        for (int it = 0; it < 2; it++) {
            int s = tid + it * 256;
            int r = s >> 2, q = (s & 3) << 2;
            float4 v = *reinterpret_cast<const float4*>(A + (size_t)(row0 + r) * K + k0 + q);
            *reinterpret_cast<float4*>(&As[r][q]) = v;
        }
        {
            int kk = tid >> 4, n4 = (tid & 15) << 2;
            int gc = col0 + n4;
            float4 v;
            if (gc + 4 <= N) {
                v = *reinterpret_cast<const float4*>(B + (size_t)(k0 + kk) * N + gc);
            } else {
                v.x = (gc + 0 < N) ? B[(size_t)(k0 + kk) * N + gc + 0] : 0.f;
                v.y = (gc + 1 < N) ? B[(size_t)(k0 + kk) * N + gc + 1] : 0.f;
                v.z = (gc + 2 < N) ? B[(size_t)(k0 + kk) * N + gc + 2] : 0.f;
                v.w = (gc + 3 < N) ? B[(size_t)(k0 + kk) * N + gc + 3] : 0.f;
            }
            *reinterpret_cast<float4*>(&Bs[kk][n4]) = v;
        }
        __syncthreads();
        #pragma unroll
        for (int k = 0; k < 16; k++) {
            float a[8], b[4];
            #pragma unroll
            for (int i = 0; i < 8; i++) a[i] = As[ty + 16 * i][k];
            #pragma unroll
            for (int j = 0; j < 4; j++) b[j] = Bs[k][tx + 16 * j];
            #pragma unroll
            for (int i = 0; i < 8; i++)
                #pragma unroll
                for (int j = 0; j < 4; j++)
                    acc[i][j] = fmaf(a[i], b[j], acc[i][j]);
        }
        __syncthreads();
    }
    #pragma unroll
    for (int i = 0; i < 8; i++) {
        int r = row0 + ty + 16 * i;
        #pragma unroll
        for (int j = 0; j < 4; j++) {
            int c = col0 + tx + 16 * j;
            if (c < N) C[(size_t)r * ldc + c] = acc[i][j];
        }
    }
}

// ---------------- fc1 split-K GEMM: partials over K chunks -----------------------
__global__ __launch_bounds__(256) void fc1_split()
{
    __shared__ float As[128][20];
    __shared__ float Bs[16][68];
    const int tid = threadIdx.x;
    const int tx = tid & 15, ty = tid >> 4;
    const int row0 = blockIdx.y * 128, col0 = blockIdx.x * 64;
    const int kb = blockIdx.z * FCHUNK;

    float acc[8][4] = {};
    for (int k0 = kb; k0 < kb + FCHUNK; k0 += 16) {
        #pragma unroll
        for (int it = 0; it < 2; it++) {
            int s = tid + it * 256;
            int r = s >> 2, q = (s & 3) << 2;
            float4 v = *reinterpret_cast<const float4*>(g_fppad + (size_t)(row0 + r) * KP1 + k0 + q);
            *reinterpret_cast<float4*>(&As[r][q]) = v;
        }
        {
            int kk = tid >> 4, n4 = (tid & 15) << 2;
            float4 v = *reinterpret_cast<const float4*>(g_w1pad + (size_t)(k0 + kk) * FP2 + col0 + n4);
            *reinterpret_cast<float4*>(&Bs[kk][n4]) = v;
        }
        __syncthreads();
        #pragma unroll
        for (int k = 0; k < 16; k++) {
            float a[8], b[4];
            #pragma unroll
            for (int i = 0; i < 8; i++) a[i] = As[ty + 16 * i][k];
            #pragma unroll
            for (int j = 0; j < 4; j++) b[j] = Bs[k][tx + 16 * j];
            #pragma unroll
            for (int i = 0; i < 8; i++)
                #pragma unroll
                for (int j = 0; j < 4; j++)
                    acc[i][j] = fmaf(a[i], b[j], acc[i][j]);
        }
        __syncthreads();
    }
    float* Cp = g_part + (size_t)blockIdx.z * Bsz * FP2;
    #pragma unroll
    for (int i = 0; i < 8; i++) {
        int r = row0 + ty + 16 * i;
        #pragma unroll
        for (int j = 0; j < 4; j++) {
            int c = col0 + tx + 16 * j;
            Cp[(size_t)r * FP2 + c] = acc[i][j];
        }
    }
}
__global__ void fc1_reduce(const float* __restrict__ fc1_b) {
    int t = blockIdx.x * blockDim.x + threadIdx.x;
    if (t >= Bsz * FP2) return;
    float s = 0.f;
    #pragma unroll
    for (int z = 0; z < FSPLIT; z++) s += g_part[(size_t)z * Bsz * FP2 + t];
    g_t1[t] = fmaxf(s + fc1_b[t & (FP2 - 1)], 0.f);
}

// ---------------- gat1: softmax probs to smem (transposed) + GEMM AV -------------
// dyn smem: Ws[128*68] + Pt[128*129] + ss[128] + dd[128]
#define G1_SM ((128*68 + 128*129 + 256) * 4)
__global__ __launch_bounds__(256) void gat1_kernel(const float* __restrict__ a_heads,
                                                   const int* __restrict__ adj)
{
    extern __shared__ float sm[];
    float* Ws = sm;                 // [j*68 + d]
    float* Pt = Ws + 128 * 68;      // [j*129 + i]  (transposed probs)
    float* ss = Pt + 128 * 129;
    float* dd = ss + 128;

    const int b = blockIdx.x >> 3;
    const int h = blockIdx.x & 7;
    const int tid = threadIdx.x, warp = tid >> 5, lane = tid & 31;
    const float* whbase = g_Wh + ((size_t)b * Nn) * HD + h * NHID;

    // stage Ws: 128 rows x 64 floats (float4)
    for (int s = tid; s < 2048; s += 256) {
        int j = s >> 4, q = (s & 15) << 2;
        float4 v = *reinterpret_cast<const float4*>(whbase + (size_t)j * HD + q);
        *reinterpret_cast<float4*>(&Ws[j * 68 + q]) = v;
    }
    __syncthreads();

    // scores
    const float* a1 = a_heads + h * (2 * NHID);
    const float* a2 = a1 + NHID;
    for (int j = warp; j < 128; j += 8) {
        float w0 = Ws[j * 68 + lane], w1 = Ws[j * 68 + lane + 32];
        float s1 = fmaf(w0, a1[lane], w1 * a1[lane + 32]);
        float s2 = fmaf(w0, a2[lane], w1 * a2[lane + 32]);
        s1 = warp_sum(s1); s2 = warp_sum(s2);
        if (lane == 0) { ss[j] = s1; dd[j] = s2; }
    }
    __syncthreads();

    // masked softmax rows -> Pt[j][i]
    const int* adjb = adj + (size_t)b * Nn * Nn;
    for (int i = warp; i < 128; i += 8) {
        const float si = ss[i];
        const int* ar = adjb + i * Nn;
        float ev[4];
        #pragma unroll
        for (int q = 0; q < 4; q++) {
            int j = lane + q * 32;
            float e = si + dd[j];
            e = (e > 0.f) ? e : ALPHA * e;
            ev[q] = (ar[j] > 0) ? e : NEGV;
        }
        float mx = fmaxf(fmaxf(ev[0], ev[1]), fmaxf(ev[2], ev[3]));
        mx = warp_max(mx);
        mx = __shfl_sync(0xffffffffu, mx, 0);
        float ls = 0.f;
        #pragma unroll
        for (int q = 0; q < 4; q++) { ev[q] = expf(ev[q] - mx); ls += ev[q]; }
        ls = warp_sum(ls);
        ls = __shfl_sync(0xffffffffu, ls, 0);
        const float inv = 1.f / ls;
        #pragma unroll
        for (int q = 0; q < 4; q++) Pt[(lane + 32 * q) * 129 + i] = ev[q] * inv;
    }
    __syncthreads();

    // AV: O(128x64) = P(128x128) @ Ws(128x64), 8x4 accum per thread
    const int tx = tid & 15, ty = tid >> 4;
    float acc[8][4] = {};
    #pragma unroll 4
    for (int k = 0; k < 128; k++) {
        float a[8], bv[4];
        #pragma unroll
        for (int i = 0; i < 8; i++) a[i] = Pt[k * 129 + ty + 16 * i];
        #pragma unroll
        for (int j = 0; j < 4; j++) bv[j] = Ws[k * 68 + tx + 16 * j];
        #pragma unroll
        for (int i = 0; i < 8; i++)
            #pragma unroll
            for (int j = 0; j < 4; j++)
                acc[i][j] = fmaf(a[i], bv[j], acc[i][j]);
    }
    float* outb = g_h + ((size_t)b * Nn) * HD + h * NHID;
    #pragma unroll
    for (int i = 0; i < 8; i++) {
        int r = ty + 16 * i;
        #pragma unroll
        for (int j = 0; j < 4; j++) {
            int c = tx + 16 * j;
            float v = acc[i][j];
            v = (v > 0.f) ? v : expm1f(v);
            outb[(size_t)r * HD + c] = v;
        }
    }
}

// ---------------- gat2 stage A: scores ------------------------------------------
__global__ __launch_bounds__(256) void score2_kernel(const float* __restrict__ a_out)
{
    const int b = blockIdx.x;
    const int tid = threadIdx.x, warp = tid >> 5, lane = tid & 31;
    const float* W = g_Wh2 + (size_t)b * Nn * HID;
    for (int j = warp; j < 128; j += 8) {
        float s1 = 0.f, s2 = 0.f;
        #pragma unroll
        for (int t = 0; t < 10; t++) {
            int d = lane + 32 * t;
            if (d < HID) {
                float w = W[(size_t)j * HID + d];
                s1 = fmaf(w, a_out[d], s1);
                s2 = fmaf(w, a_out[HID + d], s2);
            }
        }
        s1 = warp_sum(s1); s2 = warp_sum(s2);
        if (lane == 0) { g_ss2[b * Nn + j] = s1; g_dd2[b * Nn + j] = s2; }
    }
}

// ---------------- gat2 stage B: masked softmax probs -> global -------------------
__global__ __launch_bounds__(256) void prob2_kernel(const int* __restrict__ adj)
{
    __shared__ float dds[128];
    const int b = blockIdx.x;
    const int tid = threadIdx.x, warp = tid >> 5, lane = tid & 31;
    for (int t = tid; t < 128; t += 256) dds[t] = g_dd2[b * Nn + t];
    __syncthreads();
    for (int i = warp; i < 128; i += 8) {
        const float si = g_ss2[b * Nn + i];
        const int* ar = adj + ((size_t)b * Nn + i) * Nn;
        float ev[4];
        #pragma unroll
        for (int q = 0; q < 4; q++) {
            int j = lane + q * 32;
            float e = si + dds[j];
            e = (e > 0.f) ? e : ALPHA * e;
            ev[q] = (ar[j] > 0) ? e : NEGV;
        }
        float mx = fmaxf(fmaxf(ev[0], ev[1]), fmaxf(ev[2], ev[3]));
        mx = warp_max(mx);
        mx = __shfl_sync(0xffffffffu, mx, 0);
        float ls = 0.f;
        #pragma unroll
        for (int q = 0; q < 4; q++) { ev[q] = expf(ev[q] - mx); ls += ev[q]; }
        ls = warp_sum(ls);
        ls = __shfl_sync(0xffffffffu, ls, 0);
        const float inv = 1.f / ls;
        float* pr = g_P + ((size_t)b * Nn + i) * Nn;
        #pragma unroll
        for (int q = 0; q < 4; q++) pr[lane + 32 * q] = ev[q] * inv;
    }
}

// ---------------- gat2 stage C: batched AV GEMM + elu ----------------------------
// grid (5, Bsz); O[b] = elu(P[b](128x128) @ Wh2[b](128x300))
__global__ __launch_bounds__(256) void av2_kernel()
{
    __shared__ float As[128][20];
    __shared__ float Bs[16][68];
    const int b = blockIdx.y;
    const int col0 = blockIdx.x * 64;
    const int tid = threadIdx.x;
    const int tx = tid & 15, ty = tid >> 4;
    const float* A = g_P   + (size_t)b * Nn * Nn;
    const float* B = g_Wh2 + (size_t)b * Nn * HID;
    float*       C = g_O   + (size_t)b * Nn * HID;

    float acc[8][4] = {};
    for (int k0 = 0; k0 < 128; k0 += 16) {
        #pragma unroll
        for (int it = 0; it < 2; it++) {
            int s = tid + it * 256;
            int r = s >> 2, q = (s & 3) << 2;
            float4 v = *reinterpret_cast<const float4*>(A + (size_t)r * Nn + k0 + q);
            *reinterpret_cast<float4*>(&As[r][q]) = v;
        }
        {
            int kk = tid >> 4, n4 = (tid & 15) << 2;
            int gc = col0 + n4;
            float4 v;
            if (gc + 4 <= HID) {
                v = *reinterpret_cast<const float4*>(B + (size_t)(k0 + kk) * HID + gc);
            } else {
                v.x = (gc + 0 < HID) ? B[(size_t)(k0 + kk) * HID + gc + 0] : 0.f;
                v.y = (gc + 1 < HID) ? B[(size_t)(k0 + kk) * HID + gc + 1] : 0.f;
                v.z = (gc + 2 < HID) ? B[(size_t)(k0 + kk) * HID + gc + 2] : 0.f;
                v.w = (gc + 3 < HID) ? B[(size_t)(k0 + kk) * HID + gc + 3] : 0.f;
            }
            *reinterpret_cast<float4*>(&Bs[kk][n4]) = v;
        }
        __syncthreads();
        #pragma unroll
        for (int k = 0; k < 16; k++) {
            float a[8], bv[4];
            #pragma unroll
            for (int i = 0; i < 8; i++) a[i] = As[ty + 16 * i][k];
            #pragma unroll
            for (int j = 0; j < 4; j++) bv[j] = Bs[k][tx + 16 * j];
            #pragma unroll
            for (int i = 0; i < 8; i++)
                #pragma unroll
                for (int j = 0; j < 4; j++)
                    acc[i][j] = fmaf(a[i], bv[j], acc[i][j]);
        }
        __syncthreads();
    }
    #pragma unroll
    for (int i = 0; i < 8; i++) {
        int r = ty + 16 * i;
        #pragma unroll
        for (int j = 0; j < 4; j++) {
            int c = col0 + tx + 16 * j;
            if (c < HID) {
                float v = acc[i][j];
                v = (v > 0.f) ? v : expm1f(v);
                C[(size_t)r * HID + c] = v;
            }
        }
    }
}

// ---------------- gat2 stage D: log_softmax + mean -------------------------------
__global__ __launch_bounds__(256) void ls2_kernel()
{
    __shared__ float acc[8 * HID];
    const int b = blockIdx.x;
    const int tid = threadIdx.x, warp = tid >> 5, lane = tid & 31;
    for (int t = tid; t < 8 * HID; t += 256) acc[t] = 0.f;
    __syncthreads();

    const float* O = g_O + (size_t)b * Nn * HID;
    float* accw = acc + warp * HID;
    for (int i = warp; i < 128; i += 8) {
        float o[10];
        #pragma unroll
        for (int t = 0; t < 10; t++) {
            int d = lane + 32 * t;
            o[t] = (d < HID) ? O[(size_t)i * HID + d] : -1e30f;
        }
        float m = o[0];
        #pragma unroll
        for (int t = 1; t < 10; t++) m = fmaxf(m, o[t]);
        m = warp_max(m);
        m = __shfl_sync(0xffffffffu, m, 0);
        float se = 0.f;
        #pragma unroll
        for (int t = 0; t < 10; t++) se += expf(o[t] - m);
        se = warp_sum(se);
        se = __shfl_sync(0xffffffffu, se, 0);
        const float lse = m + logf(se);
        #pragma unroll
        for (int t = 0; t < 10; t++) {
            int d = lane + 32 * t;
            if (d < HID) accw[d] += o[t] - lse;
        }
    }
    __syncthreads();
    for (int d = tid; d < HID; d += 256) {
        float s = 0.f;
        #pragma unroll
        for (int w = 0; w < 8; w++) s += acc[w * HID + d];
        g_gat[b * HID + d] = s * (1.f / 128.f);
    }
}

// ---------------- head: fc2 + fc_gat + fc_fpn + ffn1 + ffn2 + sigmoid ------------
#define HB 4
__global__ __launch_bounds__(256) void head_fused(
    const float* __restrict__ fc2_w, const float* __restrict__ fc2_b,
    const float* __restrict__ Wg,    const float* __restrict__ bg,
    const float* __restrict__ Wf,    const float* __restrict__ bf,
    const float* __restrict__ W1,    const float* __restrict__ b1,
    const float* __restrict__ w2,    const float* __restrict__ b2,
    float* __restrict__ out)
{
    __shared__ float t1s [HB][512];
    __shared__ float gats[HB][HID];
    __shared__ float fpns[HB][HID];
    __shared__ float us  [HB][HID];
    __shared__ float vs  [HB][HID];
    __shared__ float ys  [HB][HID];

    const int b0 = blockIdx.x * HB;
    const int tid = threadIdx.x;

    for (int t = tid; t < HB * 512; t += 256) {
        int r = t >> 9;
        t1s[r][t & 511] = g_t1[(size_t)(b0 + r) * FP2 + (t & 511)];
    }
    for (int t = tid; t < HB * HID; t += 256) {
        int r = t / HID, c = t - r * HID;
        gats[r][c] = g_gat[(size_t)(b0 + r) * HID + c];
    }
    __syncthreads();

    for (int c = tid; c < HID; c += 256) {
        float a[HB] = {};
        #pragma unroll 4
        for (int k = 0; k < 512; k++) {
            float w = fc2_w[(size_t)k * HID + c];
            #pragma unroll
            for (int r = 0; r < HB; r++) a[r] = fmaf(t1s[r][k], w, a[r]);
        }
        float bb = fc2_b[c];
        #pragma unroll
        for (int r = 0; r < HB; r++) fpns[r][c] = a[r] + bb;
    }
    __syncthreads();

    for (int c = tid; c < HID; c += 256) {
        float a[HB] = {}, e[HB] = {};
        #pragma unroll 4
        for (int k = 0; k < HID; k++) {
            float wg = Wg[(size_t)k * HID + c];
            float wf = Wf[(size_t)k * HID + c];
            #pragma unroll
            for (int r = 0; r < HB; r++) {
                a[r] = fmaf(gats[r][k], wg, a[r]);
                e[r] = fmaf(fpns[r][k], wf, e[r]);
            }
        }
        float bbg = bg[c], bbf = bf[c];
        #pragma unroll
        for (int r = 0; r < HB; r++) {
            us[r][c] = fmaxf(a[r] + bbg, 0.f);
            vs[r][c] = fmaxf(e[r] + bbf, 0.f);
        }
    }
    __syncthreads();

    for (int c = tid; c < HID; c += 256) {
        float a[HB] = {};
        #pragma unroll 4
        for (int k = 0; k < HID; k++) {
            float w = W1[(size_t)k * HID + c];
            #pragma unroll
            for (int r = 0; r < HB; r++) a[r] = fmaf(us[r][k], w, a[r]);
        }
        #pragma unroll 4
        for (int k = 0; k < HID; k++) {
            float w = W1[(size_t)(k + HID) * HID + c];
            #pragma unroll
            for (int r = 0; r < HB; r++) a[r] = fmaf(vs[r][k], w, a[r]);
        }
        float bb = b1[c];
        #pragma unroll
        for (int r = 0; r < HB; r++) ys[r][c] = fmaxf(a[r] + bb, 0.f);
    }
    __syncthreads();

    const int warp = tid >> 5, lane = tid & 31;
    if (warp < HB) {
        float s = 0.f;
        for (int k = lane; k < HID; k += 32) s = fmaf(ys[warp][k], w2[k], s);
        s = warp_sum(s);
        if (lane == 0) out[b0 + warp] = 1.f / (1.f + expf(-(s + b2[0])));
    }
}

// ---------------- launch ----------------
extern "C" void kernel_launch(void* const* d_in, const int* in_sizes, int n_in,
                              void* d_out, int out_size)
{
    const float* atom_feats = (const float*)d_in[0];
    const float* fp         = (const float*)d_in[1];
    const float* W_heads    = (const float*)d_in[2];
    const float* a_heads    = (const float*)d_in[3];
    const float* W_out      = (const float*)d_in[4];
    const float* a_out      = (const float*)d_in[5];
    const float* fc1_w      = (const float*)d_in[6];
    const float* fc1_b      = (const float*)d_in[7];
    const float* fc2_w      = (const float*)d_in[8];
    const float* fc2_b      = (const float*)d_in[9];
    const float* fc_gat_w   = (const float*)d_in[10];
    const float* fc_gat_b   = (const float*)d_in[11];
    const float* fc_fpn_w   = (const float*)d_in[12];
    const float* fc_fpn_b   = (const float*)d_in[13];
    const float* ffn_w1     = (const float*)d_in[14];
    const float* ffn_b1     = (const float*)d_in[15];
    const float* ffn_w2     = (const float*)d_in[16];
    const float* ffn_b2     = (const float*)d_in[17];
    const int*   adj        = (const int*)  d_in[18];
    float* out = (float*)d_out;

    float *pApad, *pWt, *pWh, *ph, *pWh2;
    cudaGetSymbolAddress((void**)&pApad, g_Apad);
    cudaGetSymbolAddress((void**)&pWt,   g_Wt);
    cudaGetSymbolAddress((void**)&pWh,   g_Wh);
    cudaGetSymbolAddress((void**)&ph,    g_h);
    cudaGetSymbolAddress((void**)&pWh2,  g_Wh2);

    cudaFuncSetAttribute(gat1_kernel, cudaFuncAttributeMaxDynamicSharedMemorySize, G1_SM);

    // 1: pad A
    pad_atoms<<<(Bsz * Nn * KP + 255) / 256, 256>>>(atom_feats);
    // 2: transpose W_heads
    transpose_wheads<<<(KP * HD + 255) / 256, 256>>>(W_heads);
    // 3: K1 Wh = Apad @ Wt
    gemm128<<<dim3(HD / 64, (Bsz * Nn) / 128), 256>>>(
        pApad, pWt, pWh, Bsz * Nn, HD, KP, HD);
    // 4,5: fp pads
    pad_fp<<<(Bsz * KP1 + 255) / 256, 256>>>(fp);
    pad_w1<<<(KP1 * FP2 + 255) / 256, 256>>>(fc1_w);
    // 6: gat1  (profiled by ncu -s 5 -c 1)
    gat1_kernel<<<Bsz * Hh, 256, G1_SM>>>(a_heads, adj);
    // 7,8: fc1 split-K + reduce
    fc1_split<<<dim3(FP2 / 64, Bsz / 128, FSPLIT), 256>>>();
    fc1_reduce<<<(Bsz * FP2 + 255) / 256, 256>>>(fc1_b);
    // 9: K3 Wh2 = h @ W_out
    gemm128<<<dim3((HID + 63) / 64, (Bsz * Nn) / 128), 256>>>(
        ph, W_out, pWh2, Bsz * Nn, HID, HD, HID);
    // 10-13: gat layer 2
    score2_kernel<<<Bsz, 256>>>(a_out);
    prob2_kernel<<<Bsz, 256>>>(adj);
    av2_kernel<<<dim3(5, Bsz), 256>>>();
    ls2_kernel<<<Bsz, 256>>>();
    // 14: fused head
    head_fused<<<Bsz / HB, 256>>>(
        fc2_w, fc2_b, fc_gat_w, fc_gat_b, fc_fpn_w, fc_fpn_b,
        ffn_w1, ffn_b1, ffn_w2, ffn_b2, out);
}